// round 1
// baseline (speedup 1.0000x reference)
#include <cuda_runtime.h>
#include <math.h>

// Problem constants
#define B_     256
#define C_     8
#define L_     4096
#define D_     2048
#define PERCAM 32
#define NTOT   (C_*L_)      // 32768
#define INVB   20.0f        // 1/BETA
#define TOPK   50

// ---------------- scratch (device globals; no allocations allowed) -------
__device__ __align__(128) float g_fn[B_ * D_];
__device__ __align__(128) float g_new[B_ * D_];
__device__ __align__(128) float g_sims[(size_t)B_ * NTOT];   // 32 MB
__device__ float g_ce[B_];
__device__ float g_per[B_];

// ---------------- packed f32x2 helpers (sm_103a) -------------------------
__device__ __forceinline__ unsigned long long pk2(float x, float y) {
    unsigned long long r;
    asm("mov.b64 %0, {%1,%2};" : "=l"(r) : "f"(x), "f"(y));
    return r;
}
__device__ __forceinline__ void fma2(unsigned long long& d, unsigned long long a,
                                     unsigned long long b) {
    asm("fma.rn.f32x2 %0, %1, %2, %3;" : "=l"(d) : "l"(a), "l"(b), "l"(d));
}
__device__ __forceinline__ float2 up2(unsigned long long v) {
    float2 f;
    asm("mov.b64 {%0,%1}, %2;" : "=f"(f.x), "=f"(f.y) : "l"(v));
    return f;
}

// ---------------- Kernel 1: normalize features + EMA-updated rows --------
__global__ void __launch_bounds__(256) prep_kernel(
    const float* __restrict__ feat, const int* __restrict__ targets,
    const int* __restrict__ cams, const float* __restrict__ mem0)
{
    int i = blockIdx.x, t = threadIdx.x;
    int lane = t & 31, w = t >> 5;
    const float4* f4 = (const float4*)(feat + (size_t)i * D_);
    int cam = cams[i], tg = targets[i];
    const float4* o4 = (const float4*)(mem0 + ((size_t)cam * L_ + tg) * D_);

    float4 fa = f4[t], fb = f4[t + 256];
    float4 oa = o4[t], ob = o4[t + 256];
    float4 na, nb;
    na.x = 0.01f*oa.x + 0.99f*fa.x;  na.y = 0.01f*oa.y + 0.99f*fa.y;
    na.z = 0.01f*oa.z + 0.99f*fa.z;  na.w = 0.01f*oa.w + 0.99f*fa.w;
    nb.x = 0.01f*ob.x + 0.99f*fb.x;  nb.y = 0.01f*ob.y + 0.99f*fb.y;
    nb.z = 0.01f*ob.z + 0.99f*fb.z;  nb.w = 0.01f*ob.w + 0.99f*fb.w;

    float sf = fa.x*fa.x + fa.y*fa.y + fa.z*fa.z + fa.w*fa.w
             + fb.x*fb.x + fb.y*fb.y + fb.z*fb.z + fb.w*fb.w;
    float sn = na.x*na.x + na.y*na.y + na.z*na.z + na.w*na.w
             + nb.x*nb.x + nb.y*nb.y + nb.z*nb.z + nb.w*nb.w;

    __shared__ float shf[8], shn[8];
    __shared__ float s_rf, s_rn;
    #pragma unroll
    for (int o = 16; o; o >>= 1) {
        sf += __shfl_xor_sync(0xffffffffu, sf, o);
        sn += __shfl_xor_sync(0xffffffffu, sn, o);
    }
    if (lane == 0) { shf[w] = sf; shn[w] = sn; }
    __syncthreads();
    if (t == 0) {
        float a = 0.f, b = 0.f;
        #pragma unroll
        for (int k = 0; k < 8; k++) { a += shf[k]; b += shn[k]; }
        s_rf = rsqrtf(a); s_rn = rsqrtf(b);
    }
    __syncthreads();
    float rf = s_rf, rn = s_rn;

    float4* fo = (float4*)(g_fn + (size_t)i * D_);
    float4* no = (float4*)(g_new + (size_t)i * D_);
    fo[t]       = make_float4(fa.x*rf, fa.y*rf, fa.z*rf, fa.w*rf);
    fo[t + 256] = make_float4(fb.x*rf, fb.y*rf, fb.z*rf, fb.w*rf);
    no[t]       = make_float4(na.x*rn, na.y*rn, na.z*rn, na.w*rn);
    no[t + 256] = make_float4(nb.x*rn, nb.y*rn, nb.z*rn, nb.w*rn);
}

// ---------------- Kernel 2: sims = fn @ mem0^T  (256 x 32768, K=2048) ----
// 128x128 tile, BK=16, 256 threads, 8x8 microtile, packed f32x2 FMA,
// double-buffered shared memory.
__global__ void __launch_bounds__(256) gemm_kernel(const float* __restrict__ Bm)
{
    __shared__ float As[2][16][128];
    __shared__ float Bs[2][16][128];
    const int tid = threadIdx.x;
    const int i0 = blockIdx.y * 128;
    const int j0 = blockIdx.x * 128;
    const int r0 = tid >> 2;          // 0..63
    const int c0 = (tid & 3) * 4;     // 0,4,8,12
    const float* Ag  = g_fn + (size_t)(i0 + r0) * D_ + c0;
    const float* Ag2 = Ag + (size_t)64 * D_;
    const float* Bg  = Bm + (size_t)(j0 + r0) * D_ + c0;
    const float* Bg2 = Bg + (size_t)64 * D_;
    const int tx = tid & 15, ty = tid >> 4;

    unsigned long long acc[8][4];
    #pragma unroll
    for (int m = 0; m < 8; m++)
        #pragma unroll
        for (int n = 0; n < 4; n++) acc[m][n] = 0ull;

    // preload tile 0
    {
        float4 a0 = *(const float4*)Ag;
        float4 a1 = *(const float4*)Ag2;
        float4 b0 = *(const float4*)Bg;
        float4 b1 = *(const float4*)Bg2;
        As[0][c0+0][r0] = a0.x; As[0][c0+1][r0] = a0.y;
        As[0][c0+2][r0] = a0.z; As[0][c0+3][r0] = a0.w;
        As[0][c0+0][r0+64] = a1.x; As[0][c0+1][r0+64] = a1.y;
        As[0][c0+2][r0+64] = a1.z; As[0][c0+3][r0+64] = a1.w;
        Bs[0][c0+0][r0] = b0.x; Bs[0][c0+1][r0] = b0.y;
        Bs[0][c0+2][r0] = b0.z; Bs[0][c0+3][r0] = b0.w;
        Bs[0][c0+0][r0+64] = b1.x; Bs[0][c0+1][r0+64] = b1.y;
        Bs[0][c0+2][r0+64] = b1.z; Bs[0][c0+3][r0+64] = b1.w;
    }
    __syncthreads();

    int cur = 0;
    for (int tk = 0; tk < 128; ++tk) {
        float4 na0, na1, nb0, nb1;
        if (tk < 127) {
            int koff = (tk + 1) * 16;
            na0 = *(const float4*)(Ag  + koff);
            na1 = *(const float4*)(Ag2 + koff);
            nb0 = *(const float4*)(Bg  + koff);
            nb1 = *(const float4*)(Bg2 + koff);
        }
        #pragma unroll
        for (int kk = 0; kk < 16; ++kk) {
            float4 av0 = *(const float4*)&As[cur][kk][ty * 8];
            float4 av1 = *(const float4*)&As[cur][kk][ty * 8 + 4];
            float4 bv0 = *(const float4*)&Bs[cur][kk][tx * 8];
            float4 bv1 = *(const float4*)&Bs[cur][kk][tx * 8 + 4];
            unsigned long long bb0 = pk2(bv0.x, bv0.y);
            unsigned long long bb1 = pk2(bv0.z, bv0.w);
            unsigned long long bb2 = pk2(bv1.x, bv1.y);
            unsigned long long bb3 = pk2(bv1.z, bv1.w);
            float am[8] = {av0.x, av0.y, av0.z, av0.w, av1.x, av1.y, av1.z, av1.w};
            #pragma unroll
            for (int m = 0; m < 8; m++) {
                unsigned long long aa = pk2(am[m], am[m]);
                fma2(acc[m][0], aa, bb0);
                fma2(acc[m][1], aa, bb1);
                fma2(acc[m][2], aa, bb2);
                fma2(acc[m][3], aa, bb3);
            }
        }
        int nxt = cur ^ 1;
        if (tk < 127) {
            As[nxt][c0+0][r0] = na0.x; As[nxt][c0+1][r0] = na0.y;
            As[nxt][c0+2][r0] = na0.z; As[nxt][c0+3][r0] = na0.w;
            As[nxt][c0+0][r0+64] = na1.x; As[nxt][c0+1][r0+64] = na1.y;
            As[nxt][c0+2][r0+64] = na1.z; As[nxt][c0+3][r0+64] = na1.w;
            Bs[nxt][c0+0][r0] = nb0.x; Bs[nxt][c0+1][r0] = nb0.y;
            Bs[nxt][c0+2][r0] = nb0.z; Bs[nxt][c0+3][r0] = nb0.w;
            Bs[nxt][c0+0][r0+64] = nb1.x; Bs[nxt][c0+1][r0+64] = nb1.y;
            Bs[nxt][c0+2][r0+64] = nb1.z; Bs[nxt][c0+3][r0+64] = nb1.w;
        }
        __syncthreads();
        cur = nxt;
    }

    #pragma unroll
    for (int m = 0; m < 8; m++) {
        float2 v0 = up2(acc[m][0]), v1 = up2(acc[m][1]);
        float2 v2 = up2(acc[m][2]), v3 = up2(acc[m][3]);
        size_t off = (size_t)(i0 + ty * 8 + m) * NTOT + j0 + tx * 8;
        *(float4*)(g_sims + off)     = make_float4(v0.x, v0.y, v1.x, v1.y);
        *(float4*)(g_sims + off + 4) = make_float4(v2.x, v2.y, v3.x, v3.y);
    }
}

// ---------------- Kernel 3: per-camera proxy CE --------------------------
__global__ void __launch_bounds__(256) ce_kernel(
    const int* __restrict__ targets, const int* __restrict__ cams)
{
    __shared__ float row[L_];
    __shared__ float shred[8];
    __shared__ float s_self, s_m, s_sum;
    int i = blockIdx.x, t = threadIdx.x;
    int w = t >> 5, lane = t & 31;
    int cam = cams[i];

    // copy this camera's slice of sims (pre-update memory dots)
    const float4* srow = (const float4*)(g_sims + (size_t)i * NTOT + (size_t)cam * L_);
    float4* row4 = (float4*)row;
    #pragma unroll
    for (int q = 0; q < 4; q++) row4[t + q * 256] = srow[t + q * 256];
    __syncthreads();

    // patch the 32 EMA-updated classes of this camera: dot(fn_i, new_j)
    const float4* fnp = (const float4*)(g_fn + (size_t)i * D_);
    #pragma unroll
    for (int s = 0; s < 4; s++) {
        int j = cam * PERCAM + w * 4 + s;
        const float4* nwp = (const float4*)(g_new + (size_t)j * D_);
        float a = 0.f;
        for (int q = lane; q < D_ / 4; q += 32) {
            float4 x = fnp[q], y = nwp[q];
            a += x.x*y.x + x.y*y.y + x.z*y.z + x.w*y.w;
        }
        #pragma unroll
        for (int o = 16; o; o >>= 1) a += __shfl_xor_sync(0xffffffffu, a, o);
        if (lane == 0) {
            row[targets[j]] = a;
            if (j == i) s_self = a;
        }
    }
    __syncthreads();

    // logsumexp over 4096 logits (= row * INVB)
    float m = -1e30f;
    #pragma unroll
    for (int q = 0; q < 16; q++) m = fmaxf(m, row[t + q * 256]);
    #pragma unroll
    for (int o = 16; o; o >>= 1) m = fmaxf(m, __shfl_xor_sync(0xffffffffu, m, o));
    if (lane == 0) shred[w] = m;
    __syncthreads();
    if (t == 0) {
        float mm = shred[0];
        #pragma unroll
        for (int k = 1; k < 8; k++) mm = fmaxf(mm, shred[k]);
        s_m = mm;
    }
    __syncthreads();
    m = s_m;
    float s = 0.f;
    #pragma unroll
    for (int q = 0; q < 16; q++) s += __expf((row[t + q * 256] - m) * INVB);
    #pragma unroll
    for (int o = 16; o; o >>= 1) s += __shfl_xor_sync(0xffffffffu, s, o);
    __syncthreads();            // shred reuse barrier
    if (lane == 0) shred[w] = s;
    __syncthreads();
    if (t == 0) {
        float tot = 0.f;
        #pragma unroll
        for (int k = 0; k < 8; k++) tot += shred[k];
        float lse = m * INVB + __logf(tot);
        g_ce[i] = lse - s_self * INVB;
    }
}

// ---------------- Kernel 4: cross-camera top-50 + soft-positive loss -----
__global__ void __launch_bounds__(256) topk_kernel(const int* __restrict__ targets)
{
    __shared__ unsigned int hist[2048];
    __shared__ float cand[2048];
    __shared__ float spos[8];
    __shared__ float sredf[8];
    __shared__ int   sredi[24];
    __shared__ float s_mx, s_floor, s_scale, s_m, s_possum;
    __shared__ int s_bstar;
    __shared__ unsigned int s_cnt;

    int i = blockIdx.x, t = threadIdx.x;
    int w = t >> 5, lane = t & 31;
    int ti = targets[i];
    const float* srow = g_sims + (size_t)i * NTOT;

    if (t < 8) spos[t] = srow[t * L_ + ti];
    for (int q = t; q < 2048; q += 256) hist[q] = 0;

    // pass 1: max + counts at candidate floors
    float mx = -1e30f; int c0 = 0, c1 = 0, c2 = 0;
    for (int j = t; j < NTOT; j += 256) {
        if ((j & (L_ - 1)) == ti) continue;   // masked positives
        float v = srow[j];
        mx = fmaxf(mx, v);
        c0 += (v >= 0.05f); c1 += (v >= 0.0f); c2 += (v >= -0.1f);
    }
    #pragma unroll
    for (int o = 16; o; o >>= 1) {
        mx = fmaxf(mx, __shfl_xor_sync(0xffffffffu, mx, o));
        c0 += __shfl_xor_sync(0xffffffffu, c0, o);
        c1 += __shfl_xor_sync(0xffffffffu, c1, o);
        c2 += __shfl_xor_sync(0xffffffffu, c2, o);
    }
    if (lane == 0) { sredf[w] = mx; sredi[w] = c0; sredi[8 + w] = c1; sredi[16 + w] = c2; }
    __syncthreads();
    if (t == 0) {
        float MX = sredf[0]; int C0 = 0, C1 = 0, C2 = 0;
        #pragma unroll
        for (int k = 0; k < 8; k++) {
            MX = fmaxf(MX, sredf[k]);
            C0 += sredi[k]; C1 += sredi[8 + k]; C2 += sredi[16 + k];
        }
        float fl;
        if      (C0 >= TOPK) fl = 0.05f;
        else if (C1 >= TOPK) fl = 0.0f;
        else if (C2 >= TOPK) fl = -0.1f;
        else                 fl = -2.0f;      // always >= TOPK (sims > -1)
        s_mx = MX; s_floor = fl;
        s_scale = 2047.0f / fmaxf(MX - fl, 1e-12f);
        s_cnt = 0;
    }
    __syncthreads();
    float fl = s_floor, sc = s_scale;

    // pass 2: histogram of upper tail
    for (int j = t; j < NTOT; j += 256) {
        if ((j & (L_ - 1)) == ti) continue;
        float v = srow[j];
        if (v >= fl) {
            int b = (int)((v - fl) * sc); b = b > 2047 ? 2047 : b;
            atomicAdd(&hist[b], 1u);
        }
    }
    __syncthreads();
    if (t == 0) {
        unsigned int cum = 0; int bs = 0;
        for (int b = 2047; b >= 0; --b) { cum += hist[b]; if (cum >= TOPK) { bs = b; break; } }
        s_bstar = bs;
    }
    __syncthreads();
    int bs = s_bstar;

    // pass 3: collect candidates (>= threshold bin)
    for (int j = t; j < NTOT; j += 256) {
        if ((j & (L_ - 1)) == ti) continue;
        float v = srow[j];
        if (v >= fl) {
            int b = (int)((v - fl) * sc); b = b > 2047 ? 2047 : b;
            if (b >= bs) {
                unsigned int idx = atomicAdd(&s_cnt, 1u);
                if (idx < 2048) cand[idx] = v;
            }
        }
    }
    __syncthreads();

    if (t == 0) {
        int n = (int)s_cnt; n = n > 2048 ? 2048 : n;
        int nex = n - TOPK;                   // exclude the nex smallest candidates
        for (int e = 0; e < nex; ++e) {
            int bi = 0; float bv = 1e30f;
            for (int q = 0; q < n; ++q)
                if (cand[q] < bv) { bv = cand[q]; bi = q; }
            cand[bi] = 1e30f;                 // sentinel: excluded
        }
        float pm = spos[0], ps = 0.f;
        #pragma unroll
        for (int q = 0; q < 8; ++q) { pm = fmaxf(pm, spos[q]); ps += spos[q]; }
        s_m = fmaxf(s_mx, pm);
        s_possum = ps;
    }
    __syncthreads();

    float m = s_m;
    float loc = 0.f;
    int n = (int)s_cnt; n = n > 2048 ? 2048 : n;
    for (int q = t; q < n; q += 256) {
        float v = cand[q];
        if (v < 1e29f) loc += __expf((v - m) * INVB);
    }
    if (t < 8) loc += __expf((spos[t] - m) * INVB);
    #pragma unroll
    for (int o = 16; o; o >>= 1) loc += __shfl_xor_sync(0xffffffffu, loc, o);
    if (lane == 0) sredf[w] = loc;
    __syncthreads();
    if (t == 0) {
        float S = 0.f;
        #pragma unroll
        for (int k = 0; k < 8; k++) S += sredf[k];
        g_per[i] = m * INVB + __logf(S) - s_possum * 0.125f * INVB;
    }
}

// ---------------- Kernel 5: final reduction ------------------------------
__global__ void __launch_bounds__(256) final_kernel(
    const int* __restrict__ epoch, float* __restrict__ out)
{
    __shared__ float sa[8], sb[8];
    int t = threadIdx.x, w = t >> 5, lane = t & 31;
    float a = g_ce[t];
    float b = g_per[t];
    #pragma unroll
    for (int o = 16; o; o >>= 1) {
        a += __shfl_xor_sync(0xffffffffu, a, o);
        b += __shfl_xor_sync(0xffffffffu, b, o);
    }
    if (lane == 0) { sa[w] = a; sb[w] = b; }
    __syncthreads();
    if (t == 0) {
        float A = 0.f, Bv = 0.f;
        #pragma unroll
        for (int k = 0; k < 8; k++) { A += sa[k]; Bv += sb[k]; }
        float loss = A * (1.0f / PERCAM);
        if (epoch[0] >= 5) loss += 0.5f * Bv * (1.0f / PERCAM);
        out[0] = loss;
    }
}

// ---------------- entry --------------------------------------------------
extern "C" void kernel_launch(void* const* d_in, const int* in_sizes, int n_in,
                              void* d_out, int out_size)
{
    const float* features = (const float*)d_in[0];
    const int*   targets  = (const int*)d_in[1];
    const int*   cams     = (const int*)d_in[2];
    const float* mem0     = (const float*)d_in[5];
    const int*   epoch    = (const int*)d_in[6];
    float* out = (float*)d_out;

    prep_kernel<<<B_, 256>>>(features, targets, cams, mem0);
    gemm_kernel<<<dim3(NTOT / 128, B_ / 128), 256>>>(mem0);
    ce_kernel<<<B_, 256>>>(targets, cams);
    topk_kernel<<<B_, 256>>>(targets);
    final_kernel<<<1, 256>>>(epoch, out);
}

// round 3
// speedup vs baseline: 4.0102x; 4.0102x over previous
#include <cuda_runtime.h>
#include <cuda_fp16.h>
#include <cstdint>
#include <math.h>

// ---------------- problem constants --------------------------------------
#define B_     256
#define C_     8
#define L_     4096
#define D_     2048
#define PERCAM 32
#define NTOT   (C_*L_)      // 32768
#define INVB   20.0f        // 1/BETA
#define TOPK   50

// ---------------- GEMM config --------------------------------------------
#define GBK      32                  // fp16 elems per K chunk
#define KCH      (D_/GBK)            // 64 chunks
#define PITCH_H  40                  // halfs per smem row (80 B, conflict-free)
#define TILE_BYTES (128*PITCH_H*2)   // 10240 per operand tile
#define STAGE_BYTES (2*TILE_BYTES)   // 20480 (A + B)
#define NSTAGES  3
#define SMEM_GEMM (NSTAGES*STAGE_BYTES)  // 61440

// ---------------- scratch (device globals) -------------------------------
__device__ __align__(128) float g_fn[B_ * D_];
__device__ __align__(128) float g_new[B_ * D_];
__device__ __align__(128) __half g_fn16[B_ * D_];
__device__ __align__(128) __half g_mem16[(size_t)NTOT * D_];   // 128 MB
__device__ __align__(128) float g_sims[(size_t)B_ * NTOT];     // 32 MB
__device__ float g_ce[B_];
__device__ float g_per[B_];

// ---------------- PTX helpers --------------------------------------------
__device__ __forceinline__ uint32_t smem_u32(const void* p) {
    uint32_t a;
    asm("{ .reg .u64 t; cvta.to.shared.u64 t, %1; cvt.u32.u64 %0, t; }"
        : "=r"(a) : "l"(p));
    return a;
}
#define CP_ASYNC16(dst, src) \
    asm volatile("cp.async.cg.shared.global [%0], [%1], 16;" :: "r"(dst), "l"(src))
#define CP_COMMIT() asm volatile("cp.async.commit_group;" ::: "memory")
#define CP_WAIT0()  asm volatile("cp.async.wait_group 0;" ::: "memory")
#define CP_WAIT1()  asm volatile("cp.async.wait_group 1;" ::: "memory")

#define LDMATRIX_X4(r0,r1,r2,r3,addr) \
    asm volatile("ldmatrix.sync.aligned.m8n8.x4.shared.b16 {%0,%1,%2,%3}, [%4];" \
                 : "=r"(r0), "=r"(r1), "=r"(r2), "=r"(r3) : "r"(addr))
#define LDMATRIX_X2(r0,r1,addr) \
    asm volatile("ldmatrix.sync.aligned.m8n8.x2.shared.b16 {%0,%1}, [%2];" \
                 : "=r"(r0), "=r"(r1) : "r"(addr))
#define MMA16816(c0,c1,c2,c3,a0,a1,a2,a3,b0,b1) \
    asm volatile("mma.sync.aligned.m16n8k16.row.col.f32.f16.f16.f32 " \
                 "{%0,%1,%2,%3}, {%4,%5,%6,%7}, {%8,%9}, {%0,%1,%2,%3};" \
                 : "+f"(c0), "+f"(c1), "+f"(c2), "+f"(c3) \
                 : "r"(a0), "r"(a1), "r"(a2), "r"(a3), "r"(b0), "r"(b1))

// ---------------- Kernel 1: normalize features + EMA rows ----------------
__global__ void __launch_bounds__(256) prep_kernel(
    const float* __restrict__ feat, const int* __restrict__ targets,
    const int* __restrict__ cams, const float* __restrict__ mem0)
{
    int i = blockIdx.x, t = threadIdx.x;
    int lane = t & 31, w = t >> 5;
    const float4* f4 = (const float4*)(feat + (size_t)i * D_);
    int cam = cams[i], tg = targets[i];
    const float4* o4 = (const float4*)(mem0 + ((size_t)cam * L_ + tg) * D_);

    float4 fa = f4[t], fb = f4[t + 256];
    float4 oa = o4[t], ob = o4[t + 256];
    float4 na, nb;
    na.x = 0.01f*oa.x + 0.99f*fa.x;  na.y = 0.01f*oa.y + 0.99f*fa.y;
    na.z = 0.01f*oa.z + 0.99f*fa.z;  na.w = 0.01f*oa.w + 0.99f*fa.w;
    nb.x = 0.01f*ob.x + 0.99f*fb.x;  nb.y = 0.01f*ob.y + 0.99f*fb.y;
    nb.z = 0.01f*ob.z + 0.99f*fb.z;  nb.w = 0.01f*ob.w + 0.99f*fb.w;

    float sf = fa.x*fa.x + fa.y*fa.y + fa.z*fa.z + fa.w*fa.w
             + fb.x*fb.x + fb.y*fb.y + fb.z*fb.z + fb.w*fb.w;
    float sn = na.x*na.x + na.y*na.y + na.z*na.z + na.w*na.w
             + nb.x*nb.x + nb.y*nb.y + nb.z*nb.z + nb.w*nb.w;

    __shared__ float shf[8], shn[8];
    __shared__ float s_rf, s_rn;
    #pragma unroll
    for (int o = 16; o; o >>= 1) {
        sf += __shfl_xor_sync(0xffffffffu, sf, o);
        sn += __shfl_xor_sync(0xffffffffu, sn, o);
    }
    if (lane == 0) { shf[w] = sf; shn[w] = sn; }
    __syncthreads();
    if (t == 0) {
        float a = 0.f, b = 0.f;
        #pragma unroll
        for (int k = 0; k < 8; k++) { a += shf[k]; b += shn[k]; }
        s_rf = rsqrtf(a); s_rn = rsqrtf(b);
    }
    __syncthreads();
    float rf = s_rf, rn = s_rn;

    float4* fo = (float4*)(g_fn + (size_t)i * D_);
    float4* no = (float4*)(g_new + (size_t)i * D_);
    float4 f0 = make_float4(fa.x*rf, fa.y*rf, fa.z*rf, fa.w*rf);
    float4 f1 = make_float4(fb.x*rf, fb.y*rf, fb.z*rf, fb.w*rf);
    fo[t]       = f0;
    fo[t + 256] = f1;
    no[t]       = make_float4(na.x*rn, na.y*rn, na.z*rn, na.w*rn);
    no[t + 256] = make_float4(nb.x*rn, nb.y*rn, nb.z*rn, nb.w*rn);

    uint2* h2 = (uint2*)(g_fn16 + (size_t)i * D_);
    __half2 h0 = __floats2half2_rn(f0.x, f0.y), h1 = __floats2half2_rn(f0.z, f0.w);
    __half2 h2b = __floats2half2_rn(f1.x, f1.y), h3 = __floats2half2_rn(f1.z, f1.w);
    h2[t]       = make_uint2(*(uint32_t*)&h0, *(uint32_t*)&h1);
    h2[t + 256] = make_uint2(*(uint32_t*)&h2b, *(uint32_t*)&h3);
}

// ---------------- Kernel 1b: mem0 fp32 -> fp16 ---------------------------
__global__ void __launch_bounds__(256) cvt_kernel(const float* __restrict__ mem0)
{
    size_t i = (size_t)blockIdx.x * 256 + threadIdx.x;   // float4 index
    float4 v = ((const float4*)mem0)[i];
    __half2 h0 = __floats2half2_rn(v.x, v.y);
    __half2 h1 = __floats2half2_rn(v.z, v.w);
    ((uint2*)g_mem16)[i] = make_uint2(*(uint32_t*)&h0, *(uint32_t*)&h1);
}

// ---------------- Kernel 2: sims = fn @ mem0^T (HMMA fp16) ---------------
// grid (2 Mtiles, 256 Ntiles); CTA = 128x128; 8 warps = 2(M)x4(N), warp 64x32.
__global__ void __launch_bounds__(256) gemm_hmma()
{
    extern __shared__ __align__(16) char smraw[];
    const int tid = threadIdx.x, l = tid & 31, w = tid >> 5;
    const int i0 = blockIdx.x * 128, j0 = blockIdx.y * 128;
    const int mw = (w >> 2) * 64, nw = (w & 3) * 32;
    const uint32_t sb = smem_u32(smraw);

    float acc[4][4][4];
    #pragma unroll
    for (int mi = 0; mi < 4; mi++)
        #pragma unroll
        for (int ni = 0; ni < 4; ni++)
            #pragma unroll
            for (int u = 0; u < 4; u++) acc[mi][ni][u] = 0.f;

    auto load_stage = [&](int s, int k0) {
        uint32_t Ab = sb + s * STAGE_BYTES;
        uint32_t Bb = Ab + TILE_BYTES;
        #pragma unroll
        for (int q = 0; q < 2; q++) {
            int ch = q * 256 + tid; int r = ch >> 2, c = ch & 3;
            CP_ASYNC16(Ab + r * (PITCH_H*2) + c * 16,
                       g_fn16 + (size_t)(i0 + r) * D_ + k0 + c * 8);
        }
        #pragma unroll
        for (int q = 0; q < 2; q++) {
            int ch = q * 256 + tid; int r = ch >> 2, c = ch & 3;
            CP_ASYNC16(Bb + r * (PITCH_H*2) + c * 16,
                       g_mem16 + (size_t)(j0 + r) * D_ + k0 + c * 8);
        }
    };

    load_stage(0, 0);    CP_COMMIT();
    load_stage(1, GBK);  CP_COMMIT();

    for (int k = 0; k < KCH; k++) {
        if (k == KCH - 1) CP_WAIT0(); else CP_WAIT1();
        __syncthreads();
        uint32_t Ab = sb + (k % 3) * STAGE_BYTES;
        uint32_t Bb = Ab + TILE_BYTES;
        #pragma unroll
        for (int ks = 0; ks < 2; ks++) {
            uint32_t a[4][4], b[4][2];
            #pragma unroll
            for (int mi = 0; mi < 4; mi++) {
                uint32_t addr = Ab + (mw + mi * 16 + (l & 15)) * (PITCH_H*2)
                              + (l >> 4) * 16 + ks * 32;
                LDMATRIX_X4(a[mi][0], a[mi][1], a[mi][2], a[mi][3], addr);
            }
            #pragma unroll
            for (int ni = 0; ni < 4; ni++) {
                uint32_t addr = Bb + (nw + ni * 8 + (l & 7)) * (PITCH_H*2)
                              + ((l >> 3) & 1) * 16 + ks * 32;
                LDMATRIX_X2(b[ni][0], b[ni][1], addr);
            }
            #pragma unroll
            for (int mi = 0; mi < 4; mi++)
                #pragma unroll
                for (int ni = 0; ni < 4; ni++)
                    MMA16816(acc[mi][ni][0], acc[mi][ni][1], acc[mi][ni][2], acc[mi][ni][3],
                             a[mi][0], a[mi][1], a[mi][2], a[mi][3],
                             b[ni][0], b[ni][1]);
        }
        if (k + 2 < KCH) { load_stage((k + 2) % 3, (k + 2) * GBK); CP_COMMIT(); }
    }

    // epilogue: thread (g = l>>2, tig = l&3)
    const int g = l >> 2, tig = l & 3;
    #pragma unroll
    for (int mi = 0; mi < 4; mi++) {
        #pragma unroll
        for (int ni = 0; ni < 4; ni++) {
            size_t row = (size_t)(i0 + mw + mi * 16 + g);
            size_t col = j0 + nw + ni * 8 + tig * 2;
            float2* p0 = (float2*)(g_sims + row * NTOT + col);
            float2* p1 = (float2*)(g_sims + (row + 8) * NTOT + col);
            *p0 = make_float2(acc[mi][ni][0], acc[mi][ni][1]);
            *p1 = make_float2(acc[mi][ni][2], acc[mi][ni][3]);
        }
    }
}

// ---------------- Kernel 3: per-camera proxy CE --------------------------
__global__ void __launch_bounds__(256) ce_kernel(
    const int* __restrict__ targets, const int* __restrict__ cams)
{
    __shared__ float row[L_];
    __shared__ float shred[8];
    __shared__ float s_self, s_m;
    int i = blockIdx.x, t = threadIdx.x;
    int w = t >> 5, lane = t & 31;
    int cam = cams[i];

    const float4* srow = (const float4*)(g_sims + (size_t)i * NTOT + (size_t)cam * L_);
    float4* row4 = (float4*)row;
    #pragma unroll
    for (int q = 0; q < 4; q++) row4[t + q * 256] = srow[t + q * 256];
    __syncthreads();

    const float4* fnp = (const float4*)(g_fn + (size_t)i * D_);
    #pragma unroll
    for (int s = 0; s < 4; s++) {
        int j = cam * PERCAM + w * 4 + s;
        const float4* nwp = (const float4*)(g_new + (size_t)j * D_);
        float a = 0.f;
        for (int q = lane; q < D_ / 4; q += 32) {
            float4 x = fnp[q], y = nwp[q];
            a += x.x*y.x + x.y*y.y + x.z*y.z + x.w*y.w;
        }
        #pragma unroll
        for (int o = 16; o; o >>= 1) a += __shfl_xor_sync(0xffffffffu, a, o);
        if (lane == 0) {
            row[targets[j]] = a;
            if (j == i) s_self = a;
        }
    }
    __syncthreads();

    float m = -1e30f;
    #pragma unroll
    for (int q = 0; q < 16; q++) m = fmaxf(m, row[t + q * 256]);
    #pragma unroll
    for (int o = 16; o; o >>= 1) m = fmaxf(m, __shfl_xor_sync(0xffffffffu, m, o));
    if (lane == 0) shred[w] = m;
    __syncthreads();
    if (t == 0) {
        float mm = shred[0];
        #pragma unroll
        for (int k = 1; k < 8; k++) mm = fmaxf(mm, shred[k]);
        s_m = mm;
    }
    __syncthreads();
    m = s_m;
    float s = 0.f;
    #pragma unroll
    for (int q = 0; q < 16; q++) s += __expf((row[t + q * 256] - m) * INVB);
    #pragma unroll
    for (int o = 16; o; o >>= 1) s += __shfl_xor_sync(0xffffffffu, s, o);
    __syncthreads();
    if (lane == 0) shred[w] = s;
    __syncthreads();
    if (t == 0) {
        float tot = 0.f;
        #pragma unroll
        for (int k = 0; k < 8; k++) tot += shred[k];
        g_ce[i] = m * INVB + __logf(tot) - s_self * INVB;
    }
}

// ---------------- Kernel 4: cross-camera top-50 loss ---------------------
__global__ void __launch_bounds__(256) topk_kernel(const int* __restrict__ targets)
{
    __shared__ unsigned int hist[2048];
    __shared__ float cand[8192];
    __shared__ float cand2[256];
    __shared__ int   ssum[256];
    __shared__ float spos[8], sredf[8];
    __shared__ float s_mx, s_thr, s_scale, s_m, s_possum;
    __shared__ int   s_bstar, s_rescan;
    __shared__ unsigned int s_cnt, s_cnt2;

    int i = blockIdx.x, t = threadIdx.x, w = t >> 5, lane = t & 31;
    int ti = targets[i];
    const float* srow = g_sims + (size_t)i * NTOT;
    const float4* srow4 = (const float4*)srow;

    for (int q = t; q < 2048; q += 256) hist[q] = 0;
    if (t < 8) spos[t] = srow[t * L_ + ti];
    if (t == 0) { s_cnt = 0; s_cnt2 = 0; }
    __syncthreads();

    // single full-row scan: max + collect v >= 0.05
    float mx = -1e30f;
    for (int j4 = t; j4 < NTOT / 4; j4 += 256) {
        float4 v = srow4[j4];
        int col = (j4 << 2) & (L_ - 1);
        float a[4] = {v.x, v.y, v.z, v.w};
        #pragma unroll
        for (int u = 0; u < 4; u++) {
            if (col + u == ti) continue;
            float x = a[u];
            mx = fmaxf(mx, x);
            if (x >= 0.05f) {
                unsigned idx = atomicAdd(&s_cnt, 1u);
                if (idx < 8192) cand[idx] = x;
            }
        }
    }
    #pragma unroll
    for (int o = 16; o; o >>= 1) mx = fmaxf(mx, __shfl_xor_sync(0xffffffffu, mx, o));
    if (lane == 0) sredf[w] = mx;
    __syncthreads();
    if (t == 0) {
        float MX = sredf[0];
        #pragma unroll
        for (int k = 1; k < 8; k++) MX = fmaxf(MX, sredf[k]);
        s_mx = MX;
        if ((int)s_cnt >= TOPK) { s_thr = 0.05f; s_rescan = 0; }
        else                    { s_thr = -2.0f; s_rescan = 1; s_cnt = 0; }
    }
    __syncthreads();
    if (s_rescan) {   // rare fallback: collect everything
        for (int j4 = t; j4 < NTOT / 4; j4 += 256) {
            float4 v = srow4[j4];
            int col = (j4 << 2) & (L_ - 1);
            float a[4] = {v.x, v.y, v.z, v.w};
            #pragma unroll
            for (int u = 0; u < 4; u++) {
                if (col + u == ti) continue;
                if (a[u] >= 0.0f) {
                    unsigned idx = atomicAdd(&s_cnt, 1u);
                    if (idx < 8192) cand[idx] = a[u];
                }
            }
        }
        __syncthreads();
        if (t == 0) s_thr = 0.0f;
        __syncthreads();
    }
    if (t == 0) s_scale = 2047.0f / fmaxf(s_mx - s_thr, 1e-9f);
    __syncthreads();

    int n = (int)s_cnt; n = n > 8192 ? 8192 : n;
    float thr = s_thr, sc = s_scale;

    for (int q = t; q < n; q += 256) {
        int b = (int)((cand[q] - thr) * sc);
        b = b < 0 ? 0 : (b > 2047 ? 2047 : b);
        atomicAdd(&hist[b], 1u);
    }
    __syncthreads();
    int seg = 0;
    #pragma unroll
    for (int u = 0; u < 8; u++) seg += hist[2047 - (t * 8 + u)];
    ssum[t] = seg;
    __syncthreads();
    if (t == 0) {
        int cum = 0, bstar = 0;
        for (int s2 = 0; s2 < 256; s2++) {
            if (cum + ssum[s2] >= TOPK) {
                for (int u = 0; u < 8; u++) {
                    int b = 2047 - (s2 * 8 + u);
                    cum += hist[b];
                    if (cum >= TOPK) { bstar = b; break; }
                }
                break;
            }
            cum += ssum[s2];
        }
        s_bstar = bstar;
    }
    __syncthreads();
    int bs = s_bstar;
    for (int q = t; q < n; q += 256) {
        float x = cand[q];
        int b = (int)((x - thr) * sc);
        b = b < 0 ? 0 : (b > 2047 ? 2047 : b);
        if (b >= bs) {
            unsigned idx = atomicAdd(&s_cnt2, 1u);
            if (idx < 256) cand2[idx] = x;
        }
    }
    __syncthreads();
    if (t == 0) {
        int n2 = (int)s_cnt2; n2 = n2 > 256 ? 256 : n2;
        int nex = n2 - TOPK;
        for (int e = 0; e < nex; e++) {
            int bi = 0; float bv = 1e30f;
            for (int q = 0; q < n2; q++)
                if (cand2[q] < bv) { bv = cand2[q]; bi = q; }
            cand2[bi] = 1e30f;
        }
        float pm = spos[0], ps = 0.f;
        #pragma unroll
        for (int q = 0; q < 8; q++) { pm = fmaxf(pm, spos[q]); ps += spos[q]; }
        s_m = fmaxf(s_mx, pm);
        s_possum = ps;
    }
    __syncthreads();

    float m = s_m, loc = 0.f;
    int n2 = (int)s_cnt2; n2 = n2 > 256 ? 256 : n2;
    for (int q = t; q < n2; q += 256) {
        float v = cand2[q];
        if (v < 1e29f) loc += __expf((v - m) * INVB);
    }
    if (t < 8) loc += __expf((spos[t] - m) * INVB);
    #pragma unroll
    for (int o = 16; o; o >>= 1) loc += __shfl_xor_sync(0xffffffffu, loc, o);
    if (lane == 0) sredf[w] = loc;
    __syncthreads();
    if (t == 0) {
        float S = 0.f;
        #pragma unroll
        for (int k = 0; k < 8; k++) S += sredf[k];
        g_per[i] = m * INVB + __logf(S) - s_possum * 0.125f * INVB;
    }
}

// ---------------- Kernel 5: final reduction ------------------------------
__global__ void __launch_bounds__(256) final_kernel(
    const int* __restrict__ epoch, float* __restrict__ out)
{
    __shared__ float sa[8], sb2[8];
    int t = threadIdx.x, w = t >> 5, lane = t & 31;
    float a = g_ce[t];
    float b = g_per[t];
    #pragma unroll
    for (int o = 16; o; o >>= 1) {
        a += __shfl_xor_sync(0xffffffffu, a, o);
        b += __shfl_xor_sync(0xffffffffu, b, o);
    }
    if (lane == 0) { sa[w] = a; sb2[w] = b; }
    __syncthreads();
    if (t == 0) {
        float A = 0.f, Bv = 0.f;
        #pragma unroll
        for (int k = 0; k < 8; k++) { A += sa[k]; Bv += sb2[k]; }
        float loss = A * (1.0f / PERCAM);
        if (epoch[0] >= 5) loss += 0.5f * Bv * (1.0f / PERCAM);
        out[0] = loss;
    }
}

// ---------------- entry --------------------------------------------------
extern "C" void kernel_launch(void* const* d_in, const int* in_sizes, int n_in,
                              void* d_out, int out_size)
{
    const float* features = (const float*)d_in[0];
    const int*   targets  = (const int*)d_in[1];
    const int*   cams     = (const int*)d_in[2];
    const float* mem0     = (const float*)d_in[5];
    const int*   epoch    = (const int*)d_in[6];
    float* out = (float*)d_out;

    cudaFuncSetAttribute(gemm_hmma, cudaFuncAttributeMaxDynamicSharedMemorySize,
                         SMEM_GEMM);

    prep_kernel<<<B_, 256>>>(features, targets, cams, mem0);
    cvt_kernel<<<(NTOT * (D_ / 4)) / 256, 256>>>(mem0);
    gemm_hmma<<<dim3(2, NTOT / 128), 256, SMEM_GEMM>>>();
    ce_kernel<<<B_, 256>>>(targets, cams);
    topk_kernel<<<B_, 256>>>(targets);
    final_kernel<<<1, 256>>>(epoch, out);
}

// round 4
// speedup vs baseline: 5.0880x; 1.2688x over previous
#include <cuda_runtime.h>
#include <cuda_fp16.h>
#include <cstdint>
#include <math.h>

// ---------------- problem constants --------------------------------------
#define B_     256
#define C_     8
#define L_     4096
#define D_     2048
#define PERCAM 32
#define NTOT   (C_*L_)      // 32768
#define INVB   20.0f        // 1/BETA
#define TOPK   50

// ---------------- GEMM config --------------------------------------------
#define GBK      32                   // K elems per chunk
#define KCH      (D_/GBK)             // 64 chunks
#define PITCH_B  80                   // bytes per smem row (40 halfs)
#define A_TILE   (256*PITCH_B)        // 20480 (M=256 x 32 halfs)
#define B_TILE   (128*PITCH_B)        // 10240 (N=128 x 32 halfs)
#define A_STAGES 3
#define SMEM_GEMM (A_STAGES*A_TILE + 2*B_TILE)   // 61440+20480 = 81920

// ---------------- scratch (device globals) -------------------------------
__device__ __align__(128) float g_fn[B_ * D_];
__device__ __align__(128) float g_new[B_ * D_];
__device__ __align__(128) __half g_fn16[B_ * D_];
__device__ __align__(128) float g_sims[(size_t)B_ * NTOT];     // 32 MB
__device__ float g_ce[B_];
__device__ float g_per[B_];

// ---------------- PTX helpers --------------------------------------------
__device__ __forceinline__ uint32_t smem_u32(const void* p) {
    uint32_t a;
    asm("{ .reg .u64 t; cvta.to.shared.u64 t, %1; cvt.u32.u64 %0, t; }"
        : "=r"(a) : "l"(p));
    return a;
}
#define CP_ASYNC16(dst, src) \
    asm volatile("cp.async.cg.shared.global [%0], [%1], 16;" :: "r"(dst), "l"(src))
#define CP_COMMIT() asm volatile("cp.async.commit_group;" ::: "memory")
#define CP_WAIT0()  asm volatile("cp.async.wait_group 0;" ::: "memory")
#define CP_WAIT1()  asm volatile("cp.async.wait_group 1;" ::: "memory")

#define LDMATRIX_X4(r0,r1,r2,r3,addr) \
    asm volatile("ldmatrix.sync.aligned.m8n8.x4.shared.b16 {%0,%1,%2,%3}, [%4];" \
                 : "=r"(r0), "=r"(r1), "=r"(r2), "=r"(r3) : "r"(addr))
#define LDMATRIX_X2(r0,r1,addr) \
    asm volatile("ldmatrix.sync.aligned.m8n8.x2.shared.b16 {%0,%1}, [%2];" \
                 : "=r"(r0), "=r"(r1) : "r"(addr))
#define MMA16816(c0,c1,c2,c3,a0,a1,a2,a3,b0,b1) \
    asm volatile("mma.sync.aligned.m16n8k16.row.col.f32.f16.f16.f32 " \
                 "{%0,%1,%2,%3}, {%4,%5,%6,%7}, {%8,%9}, {%0,%1,%2,%3};" \
                 : "+f"(c0), "+f"(c1), "+f"(c2), "+f"(c3) \
                 : "r"(a0), "r"(a1), "r"(a2), "r"(a3), "r"(b0), "r"(b1))
#define STS128(addr, v0, v1, v2, v3) \
    asm volatile("st.shared.v4.b32 [%0], {%1,%2,%3,%4};" \
                 :: "r"(addr), "r"(v0), "r"(v1), "r"(v2), "r"(v3) : "memory")

// ---------------- Kernel 1: normalize features + EMA rows ----------------
__global__ void __launch_bounds__(256) prep_kernel(
    const float* __restrict__ feat, const int* __restrict__ targets,
    const int* __restrict__ cams, const float* __restrict__ mem0)
{
    int i = blockIdx.x, t = threadIdx.x;
    int lane = t & 31, w = t >> 5;
    const float4* f4 = (const float4*)(feat + (size_t)i * D_);
    int cam = cams[i], tg = targets[i];
    const float4* o4 = (const float4*)(mem0 + ((size_t)cam * L_ + tg) * D_);

    float4 fa = f4[t], fb = f4[t + 256];
    float4 oa = o4[t], ob = o4[t + 256];
    float4 na, nb;
    na.x = 0.01f*oa.x + 0.99f*fa.x;  na.y = 0.01f*oa.y + 0.99f*fa.y;
    na.z = 0.01f*oa.z + 0.99f*fa.z;  na.w = 0.01f*oa.w + 0.99f*fa.w;
    nb.x = 0.01f*ob.x + 0.99f*fb.x;  nb.y = 0.01f*ob.y + 0.99f*fb.y;
    nb.z = 0.01f*ob.z + 0.99f*fb.z;  nb.w = 0.01f*ob.w + 0.99f*fb.w;

    float sf = fa.x*fa.x + fa.y*fa.y + fa.z*fa.z + fa.w*fa.w
             + fb.x*fb.x + fb.y*fb.y + fb.z*fb.z + fb.w*fb.w;
    float sn = na.x*na.x + na.y*na.y + na.z*na.z + na.w*na.w
             + nb.x*nb.x + nb.y*nb.y + nb.z*nb.z + nb.w*nb.w;

    __shared__ float shf[8], shn[8];
    __shared__ float s_rf, s_rn;
    #pragma unroll
    for (int o = 16; o; o >>= 1) {
        sf += __shfl_xor_sync(0xffffffffu, sf, o);
        sn += __shfl_xor_sync(0xffffffffu, sn, o);
    }
    if (lane == 0) { shf[w] = sf; shn[w] = sn; }
    __syncthreads();
    if (t == 0) {
        float a = 0.f, b = 0.f;
        #pragma unroll
        for (int k = 0; k < 8; k++) { a += shf[k]; b += shn[k]; }
        s_rf = rsqrtf(a); s_rn = rsqrtf(b);
    }
    __syncthreads();
    float rf = s_rf, rn = s_rn;

    float4* fo = (float4*)(g_fn + (size_t)i * D_);
    float4* no = (float4*)(g_new + (size_t)i * D_);
    float4 f0 = make_float4(fa.x*rf, fa.y*rf, fa.z*rf, fa.w*rf);
    float4 f1 = make_float4(fb.x*rf, fb.y*rf, fb.z*rf, fb.w*rf);
    fo[t]       = f0;
    fo[t + 256] = f1;
    no[t]       = make_float4(na.x*rn, na.y*rn, na.z*rn, na.w*rn);
    no[t + 256] = make_float4(nb.x*rn, nb.y*rn, nb.z*rn, nb.w*rn);

    uint2* h2p = (uint2*)(g_fn16 + (size_t)i * D_);
    __half2 h0 = __floats2half2_rn(f0.x, f0.y), h1 = __floats2half2_rn(f0.z, f0.w);
    __half2 h2b = __floats2half2_rn(f1.x, f1.y), h3 = __floats2half2_rn(f1.z, f1.w);
    h2p[t]       = make_uint2(*(uint32_t*)&h0, *(uint32_t*)&h1);
    h2p[t + 256] = make_uint2(*(uint32_t*)&h2b, *(uint32_t*)&h3);
}

// ---------------- Kernel 2: sims = fn @ mem0^T (HMMA, fused B convert) ---
// 256 CTAs, each: M=256 (all rows) x N=128 tile. 8 warps = 4(M) x 2(N),
// warp tile 64x64. A fp16 via 3-stage cp.async; B fp32 LDG -> cvt -> STS
// fp16, double-buffered smem.
__global__ void __launch_bounds__(256, 1) gemm_hmma(const float* __restrict__ Bm)
{
    extern __shared__ __align__(16) char smraw[];
    const int tid = threadIdx.x, l = tid & 31, w = tid >> 5;
    const int j0 = blockIdx.x * 128;
    const int mw = (w >> 1) * 64, nw = (w & 1) * 64;
    const uint32_t sb = smem_u32(smraw);
    const uint32_t Bsm0 = sb + A_STAGES * A_TILE;

    float acc[4][8][4];
    #pragma unroll
    for (int mi = 0; mi < 4; mi++)
        #pragma unroll
        for (int ni = 0; ni < 8; ni++)
            #pragma unroll
            for (int u = 0; u < 4; u++) acc[mi][ni][u] = 0.f;

    const int brow = tid >> 1, bcol = (tid & 1) * 16;   // B load mapping
    const float4* bsrc_base = (const float4*)(Bm + (size_t)(j0 + brow) * D_ + bcol);
    const uint32_t bsts_base = Bsm0 + brow * PITCH_B + bcol * 2;

    auto load_A = [&](int s, int k0) {
        uint32_t Ab = sb + s * A_TILE;
        #pragma unroll
        for (int q = 0; q < 4; q++) {
            int id = q * 256 + tid; int r = id >> 2, c = id & 3;
            CP_ASYNC16(Ab + r * PITCH_B + c * 16,
                       g_fn16 + (size_t)r * D_ + k0 + c * 8);
        }
    };

    float4 br[4];
    auto ldg_B = [&](int k0) {
        const float4* s4 = bsrc_base + (k0 >> 2);
        br[0] = s4[0]; br[1] = s4[1]; br[2] = s4[2]; br[3] = s4[3];
    };
    auto sts_B = [&](int s) {
        uint32_t h[8];
        #pragma unroll
        for (int u = 0; u < 4; u++) {
            __half2 p0 = __floats2half2_rn(br[u].x, br[u].y);
            __half2 p1 = __floats2half2_rn(br[u].z, br[u].w);
            h[2*u]   = *(uint32_t*)&p0;
            h[2*u+1] = *(uint32_t*)&p1;
        }
        uint32_t a0 = bsts_base + s * B_TILE;
        STS128(a0,      h[0], h[1], h[2], h[3]);
        STS128(a0 + 16, h[4], h[5], h[6], h[7]);
    };

    load_A(0, 0);    CP_COMMIT();
    load_A(1, GBK);  CP_COMMIT();
    ldg_B(0);

    for (int k = 0; k < KCH; k++) {
        sts_B(k & 1);
        if (k == KCH - 1) CP_WAIT0(); else CP_WAIT1();
        __syncthreads();
        if (k + 1 < KCH) ldg_B((k + 1) * GBK);
        if (k + 2 < KCH) { load_A((k + 2) % 3, (k + 2) * GBK); CP_COMMIT(); }

        uint32_t Ab = sb + (k % 3) * A_TILE;
        uint32_t Bb = Bsm0 + (k & 1) * B_TILE;
        #pragma unroll
        for (int ks = 0; ks < 2; ks++) {
            uint32_t a[4][4], b[8][2];
            #pragma unroll
            for (int mi = 0; mi < 4; mi++) {
                uint32_t addr = Ab + (mw + mi * 16 + (l & 15)) * PITCH_B
                              + (l >> 4) * 16 + ks * 32;
                LDMATRIX_X4(a[mi][0], a[mi][1], a[mi][2], a[mi][3], addr);
            }
            #pragma unroll
            for (int ni = 0; ni < 8; ni++) {
                uint32_t addr = Bb + (nw + ni * 8 + (l & 7)) * PITCH_B
                              + ((l >> 3) & 1) * 16 + ks * 32;
                LDMATRIX_X2(b[ni][0], b[ni][1], addr);
            }
            #pragma unroll
            for (int mi = 0; mi < 4; mi++)
                #pragma unroll
                for (int ni = 0; ni < 8; ni++)
                    MMA16816(acc[mi][ni][0], acc[mi][ni][1], acc[mi][ni][2], acc[mi][ni][3],
                             a[mi][0], a[mi][1], a[mi][2], a[mi][3],
                             b[ni][0], b[ni][1]);
        }
    }

    const int g = l >> 2, tig = l & 3;
    #pragma unroll
    for (int mi = 0; mi < 4; mi++) {
        #pragma unroll
        for (int ni = 0; ni < 8; ni++) {
            size_t row = (size_t)(mw + mi * 16 + g);
            size_t col = j0 + nw + ni * 8 + tig * 2;
            *(float2*)(g_sims + row * NTOT + col)       = make_float2(acc[mi][ni][0], acc[mi][ni][1]);
            *(float2*)(g_sims + (row + 8) * NTOT + col) = make_float2(acc[mi][ni][2], acc[mi][ni][3]);
        }
    }
}

// ---------------- Kernel 3: per-camera proxy CE --------------------------
__global__ void __launch_bounds__(256) ce_kernel(
    const int* __restrict__ targets, const int* __restrict__ cams)
{
    __shared__ float row[L_];
    __shared__ float shred[8];
    __shared__ float s_self, s_m;
    int i = blockIdx.x, t = threadIdx.x;
    int w = t >> 5, lane = t & 31;
    int cam = cams[i];

    const float4* srow = (const float4*)(g_sims + (size_t)i * NTOT + (size_t)cam * L_);
    float4* row4 = (float4*)row;
    #pragma unroll
    for (int q = 0; q < 4; q++) row4[t + q * 256] = srow[t + q * 256];

    // patch dots: warp w handles rows j = cam*32 + w*4 .. +3, batched
    const float4* fnp = (const float4*)(g_fn + (size_t)i * D_);
    {
        int jb = cam * PERCAM + w * 4;
        const float4* y0 = (const float4*)(g_new + (size_t)(jb + 0) * D_);
        const float4* y1 = (const float4*)(g_new + (size_t)(jb + 1) * D_);
        const float4* y2 = (const float4*)(g_new + (size_t)(jb + 2) * D_);
        const float4* y3 = (const float4*)(g_new + (size_t)(jb + 3) * D_);
        float a0 = 0.f, a1 = 0.f, a2 = 0.f, a3 = 0.f;
        for (int q = lane; q < D_ / 4; q += 32) {
            float4 x = fnp[q];
            float4 v0 = y0[q], v1 = y1[q], v2 = y2[q], v3 = y3[q];
            a0 += x.x*v0.x + x.y*v0.y + x.z*v0.z + x.w*v0.w;
            a1 += x.x*v1.x + x.y*v1.y + x.z*v1.z + x.w*v1.w;
            a2 += x.x*v2.x + x.y*v2.y + x.z*v2.z + x.w*v2.w;
            a3 += x.x*v3.x + x.y*v3.y + x.z*v3.z + x.w*v3.w;
        }
        #pragma unroll
        for (int o = 16; o; o >>= 1) {
            a0 += __shfl_xor_sync(0xffffffffu, a0, o);
            a1 += __shfl_xor_sync(0xffffffffu, a1, o);
            a2 += __shfl_xor_sync(0xffffffffu, a2, o);
            a3 += __shfl_xor_sync(0xffffffffu, a3, o);
        }
        __syncthreads();   // slice copy done before patching
        if (lane == 0) {
            float av[4] = {a0, a1, a2, a3};
            #pragma unroll
            for (int s = 0; s < 4; s++) {
                int j = jb + s;
                row[targets[j]] = av[s];
                if (j == i) s_self = av[s];
            }
        }
    }
    __syncthreads();

    float m = -1e30f;
    #pragma unroll
    for (int q = 0; q < 16; q++) m = fmaxf(m, row[t + q * 256]);
    #pragma unroll
    for (int o = 16; o; o >>= 1) m = fmaxf(m, __shfl_xor_sync(0xffffffffu, m, o));
    if (lane == 0) shred[w] = m;
    __syncthreads();
    if (t == 0) {
        float mm = shred[0];
        #pragma unroll
        for (int k = 1; k < 8; k++) mm = fmaxf(mm, shred[k]);
        s_m = mm;
    }
    __syncthreads();
    m = s_m;
    float s = 0.f;
    #pragma unroll
    for (int q = 0; q < 16; q++) s += __expf((row[t + q * 256] - m) * INVB);
    #pragma unroll
    for (int o = 16; o; o >>= 1) s += __shfl_xor_sync(0xffffffffu, s, o);
    __syncthreads();
    if (lane == 0) shred[w] = s;
    __syncthreads();
    if (t == 0) {
        float tot = 0.f;
        #pragma unroll
        for (int k = 0; k < 8; k++) tot += shred[k];
        g_ce[i] = m * INVB + __logf(tot) - s_self * INVB;
    }
}

// ---------------- Kernel 4: cross-camera top-50 loss ---------------------
__global__ void __launch_bounds__(256) topk_kernel(const int* __restrict__ targets)
{
    __shared__ unsigned int hist[2048];
    __shared__ float cand[8192];
    __shared__ float cand2[256];
    __shared__ int   ssum[256];
    __shared__ float spos[8], sredf[8];
    __shared__ float s_mx, s_thr, s_scale, s_m, s_possum;
    __shared__ int   s_bstar, s_rescan;
    __shared__ unsigned int s_cnt, s_cnt2;

    int i = blockIdx.x, t = threadIdx.x, w = t >> 5, lane = t & 31;
    int ti = targets[i];
    const float* srow = g_sims + (size_t)i * NTOT;
    const float4* srow4 = (const float4*)srow;

    for (int q = t; q < 2048; q += 256) hist[q] = 0;
    if (t < 8) spos[t] = srow[t * L_ + ti];
    if (t == 0) { s_cnt = 0; s_cnt2 = 0; }
    __syncthreads();

    float mx = -1e30f;
    for (int j4 = t; j4 < NTOT / 4; j4 += 256) {
        float4 v = srow4[j4];
        int col = (j4 << 2) & (L_ - 1);
        float a[4] = {v.x, v.y, v.z, v.w};
        #pragma unroll
        for (int u = 0; u < 4; u++) {
            if (col + u == ti) continue;
            float x = a[u];
            mx = fmaxf(mx, x);
            if (x >= 0.05f) {
                unsigned idx = atomicAdd(&s_cnt, 1u);
                if (idx < 8192) cand[idx] = x;
            }
        }
    }
    #pragma unroll
    for (int o = 16; o; o >>= 1) mx = fmaxf(mx, __shfl_xor_sync(0xffffffffu, mx, o));
    if (lane == 0) sredf[w] = mx;
    __syncthreads();
    if (t == 0) {
        float MX = sredf[0];
        #pragma unroll
        for (int k = 1; k < 8; k++) MX = fmaxf(MX, sredf[k]);
        s_mx = MX;
        if ((int)s_cnt >= TOPK) { s_thr = 0.05f; s_rescan = 0; }
        else                    { s_thr = -2.0f; s_rescan = 1; s_cnt = 0; }
    }
    __syncthreads();
    if (s_rescan) {
        for (int j4 = t; j4 < NTOT / 4; j4 += 256) {
            float4 v = srow4[j4];
            int col = (j4 << 2) & (L_ - 1);
            float a[4] = {v.x, v.y, v.z, v.w};
            #pragma unroll
            for (int u = 0; u < 4; u++) {
                if (col + u == ti) continue;
                if (a[u] >= 0.0f) {
                    unsigned idx = atomicAdd(&s_cnt, 1u);
                    if (idx < 8192) cand[idx] = a[u];
                }
            }
        }
        __syncthreads();
        if (t == 0) s_thr = 0.0f;
        __syncthreads();
    }
    if (t == 0) s_scale = 2047.0f / fmaxf(s_mx - s_thr, 1e-9f);
    __syncthreads();

    int n = (int)s_cnt; n = n > 8192 ? 8192 : n;
    float thr = s_thr, sc = s_scale;

    for (int q = t; q < n; q += 256) {
        int b = (int)((cand[q] - thr) * sc);
        b = b < 0 ? 0 : (b > 2047 ? 2047 : b);
        atomicAdd(&hist[b], 1u);
    }
    __syncthreads();
    int seg = 0;
    #pragma unroll
    for (int u = 0; u < 8; u++) seg += hist[2047 - (t * 8 + u)];
    ssum[t] = seg;
    __syncthreads();
    if (t == 0) {
        int cum = 0, bstar = 0;
        for (int s2 = 0; s2 < 256; s2++) {
            if (cum + ssum[s2] >= TOPK) {
                for (int u = 0; u < 8; u++) {
                    int b = 2047 - (s2 * 8 + u);
                    cum += hist[b];
                    if (cum >= TOPK) { bstar = b; break; }
                }
                break;
            }
            cum += ssum[s2];
        }
        s_bstar = bstar;
    }
    __syncthreads();
    int bs = s_bstar;
    for (int q = t; q < n; q += 256) {
        float x = cand[q];
        int b = (int)((x - thr) * sc);
        b = b < 0 ? 0 : (b > 2047 ? 2047 : b);
        if (b >= bs) {
            unsigned idx = atomicAdd(&s_cnt2, 1u);
            if (idx < 256) cand2[idx] = x;
        }
    }
    __syncthreads();
    if (t == 0) {
        int n2 = (int)s_cnt2; n2 = n2 > 256 ? 256 : n2;
        int nex = n2 - TOPK;
        for (int e = 0; e < nex; e++) {
            int bi = 0; float bv = 1e30f;
            for (int q = 0; q < n2; q++)
                if (cand2[q] < bv) { bv = cand2[q]; bi = q; }
            cand2[bi] = 1e30f;
        }
        float pm = spos[0], ps = 0.f;
        #pragma unroll
        for (int q = 0; q < 8; q++) { pm = fmaxf(pm, spos[q]); ps += spos[q]; }
        s_m = fmaxf(s_mx, pm);
        s_possum = ps;
    }
    __syncthreads();

    float m = s_m, loc = 0.f;
    int n2 = (int)s_cnt2; n2 = n2 > 256 ? 256 : n2;
    for (int q = t; q < n2; q += 256) {
        float v = cand2[q];
        if (v < 1e29f) loc += __expf((v - m) * INVB);
    }
    if (t < 8) loc += __expf((spos[t] - m) * INVB);
    #pragma unroll
    for (int o = 16; o; o >>= 1) loc += __shfl_xor_sync(0xffffffffu, loc, o);
    if (lane == 0) sredf[w] = loc;
    __syncthreads();
    if (t == 0) {
        float S = 0.f;
        #pragma unroll
        for (int k = 0; k < 8; k++) S += sredf[k];
        g_per[i] = m * INVB + __logf(S) - s_possum * 0.125f * INVB;
    }
}

// ---------------- Kernel 5: final reduction ------------------------------
__global__ void __launch_bounds__(256) final_kernel(
    const int* __restrict__ epoch, float* __restrict__ out)
{
    __shared__ float sa[8], sb2[8];
    int t = threadIdx.x, w = t >> 5, lane = t & 31;
    float a = g_ce[t];
    float b = g_per[t];
    #pragma unroll
    for (int o = 16; o; o >>= 1) {
        a += __shfl_xor_sync(0xffffffffu, a, o);
        b += __shfl_xor_sync(0xffffffffu, b, o);
    }
    if (lane == 0) { sa[w] = a; sb2[w] = b; }
    __syncthreads();
    if (t == 0) {
        float A = 0.f, Bv = 0.f;
        #pragma unroll
        for (int k = 0; k < 8; k++) { A += sa[k]; Bv += sb2[k]; }
        float loss = A * (1.0f / PERCAM);
        if (epoch[0] >= 5) loss += 0.5f * Bv * (1.0f / PERCAM);
        out[0] = loss;
    }
}

// ---------------- entry --------------------------------------------------
extern "C" void kernel_launch(void* const* d_in, const int* in_sizes, int n_in,
                              void* d_out, int out_size)
{
    const float* features = (const float*)d_in[0];
    const int*   targets  = (const int*)d_in[1];
    const int*   cams     = (const int*)d_in[2];
    const float* mem0     = (const float*)d_in[5];
    const int*   epoch    = (const int*)d_in[6];
    float* out = (float*)d_out;

    cudaFuncSetAttribute(gemm_hmma, cudaFuncAttributeMaxDynamicSharedMemorySize,
                         SMEM_GEMM);

    prep_kernel<<<B_, 256>>>(features, targets, cams, mem0);
    gemm_hmma<<<NTOT / 128, 256, SMEM_GEMM>>>(mem0);
    ce_kernel<<<B_, 256>>>(targets, cams);
    topk_kernel<<<B_, 256>>>(targets);
    final_kernel<<<1, 256>>>(epoch, out);
}